// round 16
// baseline (speedup 1.0000x reference)
#include <cuda_runtime.h>
#include <cuda_fp16.h>

#define NN 100000
#define EE 1600000
#define HID 128
#define LN_EPS 1e-5f

// ---- GEMM-1 config: block = 128 rows x 128 cols (W1 only), 512 thr ----
#define TM_A 128
#define THR_G 512
#define GA_TOT 782               // ceil(NN / TM_A)
#define GA_H1 391
#define GA_H2 (GA_TOT - GA_H1)
#define HB_BLK 512               // hist blocks in mergeA
#define FB_BLK 512               // fill blocks in mergeB
#define SXH 136
#define SWH 136
#define SMEM_G ((TM_A * SXH + 128 * SWH) * 2)

// ---- gemm2 config ----
#define TM_F 256
#define THR_F 512
#define SHH 136
#define SW2H 136
#define SMEM_F ((TM_F * SHH + 128 * SW2H) * 2 + 512 * 4)

// ---- gather config ----
#define GB_BLK 1564
#define GW (GB_BLK * 8)          // 12512 warps
#define RPW ((NN + GW - 1) / GW) // 8 rows per warp

// ---- scan config (single-pass decoupled lookback) ----
#define NB_S 196
#define CHUNK_S 512

// ---- device scratch ----
__device__ int    g_cnt[NN];
__device__ int    g_cur[NN];
__device__ int    g_off[NN + 1];
__device__ int    g_pub[NB_S];   // packed (flag<<28)|value; 0 = not published
__device__ int    g_elist[EE];
__device__ __half g_wAt[256 * 128];  // [W1|Wres] transposed: [n][k], fp16
__device__ __half g_w2t[128 * 128];  // W2 transposed: [n][k], fp16
__device__ __half g_y1h[(size_t)NN * HID];
__device__ __half g_hh[(size_t)NN * HID];

// ---------------- helpers ----------------

__device__ __forceinline__ void mma_f16(float* c, const unsigned* a, const unsigned* b) {
  asm volatile(
      "mma.sync.aligned.m16n8k16.row.col.f32.f16.f16.f32 "
      "{%0,%1,%2,%3}, {%4,%5,%6,%7}, {%8,%9}, {%0,%1,%2,%3};"
      : "+f"(c[0]), "+f"(c[1]), "+f"(c[2]), "+f"(c[3])
      : "r"(a[0]), "r"(a[1]), "r"(a[2]), "r"(a[3]), "r"(b[0]), "r"(b[1]));
}

__device__ __forceinline__ unsigned ldh2(const __half* p) {
  return *(const unsigned*)p;
}

// ---------------- prep: zero counters + one-time weight convert/transpose ----------------

__global__ void k_prep(const float* __restrict__ W1, const float* __restrict__ Wres,
                       const float* __restrict__ W2) {
  int stride = gridDim.x * blockDim.x;
  int t0 = blockIdx.x * blockDim.x + threadIdx.x;
  for (int i = t0; i < NN; i += stride) g_cnt[i] = 0;
  if (t0 < NB_S) g_pub[t0] = 0;
  for (int i = t0; i < 256 * 128; i += stride) {
    int n = i >> 7, k = i & 127;
    float v = (n < 128) ? W1[k * 128 + n] : Wres[k * 128 + (n - 128)];
    g_wAt[i] = __float2half_rn(v);
  }
  for (int i = t0; i < 128 * 128; i += stride) {
    int n = i >> 7, k = i & 127;
    g_w2t[i] = __float2half_rn(W2[k * 128 + n]);
  }
}

// ---------------- single-pass scan (decoupled lookback) ----------------

__global__ void k_scanLB() {
  __shared__ int s[256];
  __shared__ int s_excl;
  int b = blockIdx.x, t = threadIdx.x;
  int i0 = b * CHUNK_S + t * 2;
  int c0 = (i0 < NN) ? g_cnt[i0] : 0;
  int c1 = (i0 + 1 < NN) ? g_cnt[i0 + 1] : 0;
  s[t] = c0 + c1;
  __syncthreads();
#pragma unroll
  for (int d = 1; d < 256; d <<= 1) {
    int v = (t >= d) ? s[t - d] : 0;
    __syncthreads();
    s[t] += v;
    __syncthreads();
  }
  int total = s[255];
  if (t == 0) {
    if (b == 0) {
      atomicExch(&g_pub[0], (2 << 28) | total);
      s_excl = 0;
    } else {
      atomicExch(&g_pub[b], (1 << 28) | total);
      int excl = 0, p = b - 1;
      while (1) {
        int w = atomicAdd(&g_pub[p], 0);
        if (w == 0) { __nanosleep(40); continue; }
        excl += w & 0x0FFFFFFF;
        if ((w >> 28) == 2) break;
        p--;
      }
      atomicExch(&g_pub[b], (2 << 28) | (excl + total));
      s_excl = excl;
    }
  }
  __syncthreads();
  int base = s_excl + ((t == 0) ? 0 : s[t - 1]);
  if (i0 < NN)     { g_off[i0] = base;          g_cur[i0] = base; }
  if (i0 + 1 < NN) { g_off[i0 + 1] = base + c0; g_cur[i0 + 1] = base + c0; }
  if (b == NB_S - 1 && t == 255) g_off[NN] = s_excl + total;
}

// ---------------- gemm1 body: y1 = x@W1 (128 rows x 128 cols, acc=32 regs) ----------------
// Warp (wm=warp>>2, wn=warp&3): 32 rows x 32 cols = 2 m-tiles x 4 n-tiles m16n8k16.

__device__ __forceinline__ void gemm1_body(int ba, const float* __restrict__ x) {
  extern __shared__ __half smh[];
  __half* sX  = smh;
  __half* sWT = smh + TM_A * SXH;
  int tid = threadIdx.x;
  int base = ba * TM_A;

  const uint4* wsrc = (const uint4*)g_wAt;   // W1 half
  for (int i = tid; i < 128 * 16; i += THR_G) {
    int n = i >> 4, c = i & 15;
    *(uint4*)(sWT + n * SWH + c * 8) = wsrc[i];
  }
  const float4* x4 = (const float4*)x;
  for (int i = tid; i < TM_A * 32; i += THR_G) {
    int row = i >> 5, c4 = i & 31;
    float4 v = make_float4(0.f, 0.f, 0.f, 0.f);
    if (base + row < NN) v = x4[(size_t)(base + row) * 32 + c4];
    *(__half2*)(sX + row * SXH + c4 * 4)     = __floats2half2_rn(v.x, v.y);
    *(__half2*)(sX + row * SXH + c4 * 4 + 2) = __floats2half2_rn(v.z, v.w);
  }
  __syncthreads();

  int warp = tid >> 5, lane = tid & 31;
  int gid = lane >> 2, tig = lane & 3;
  int wm = warp >> 2, wn = warp & 3;

  float acc[2][4][4];
#pragma unroll
  for (int mt = 0; mt < 2; mt++)
#pragma unroll
    for (int nt = 0; nt < 4; nt++)
#pragma unroll
      for (int r = 0; r < 4; r++) acc[mt][nt][r] = 0.f;

  const __half* pA = sX + (wm * 32 + gid) * SXH + tig * 2;
  const __half* pB = sWT + (wn * 32 + gid) * SWH + tig * 2;

#pragma unroll
  for (int kk = 0; kk < 8; kk++) {
    unsigned a[2][4];
#pragma unroll
    for (int mt = 0; mt < 2; mt++) {
      const __half* p = pA + mt * 16 * SXH + kk * 16;
      a[mt][0] = ldh2(p);
      a[mt][1] = ldh2(p + 8 * SXH);
      a[mt][2] = ldh2(p + 8);
      a[mt][3] = ldh2(p + 8 * SXH + 8);
    }
#pragma unroll
    for (int nt = 0; nt < 4; nt++) {
      const __half* q = pB + nt * 8 * SWH + kk * 16;
      unsigned b[2];
      b[0] = ldh2(q);
      b[1] = ldh2(q + 8);
      mma_f16(acc[0][nt], a[0], b);
      mma_f16(acc[1][nt], a[1], b);
    }
  }

#pragma unroll
  for (int mt = 0; mt < 2; mt++) {
    int row0 = base + wm * 32 + mt * 16 + gid;
    int row1 = row0 + 8;
#pragma unroll
    for (int nt = 0; nt < 4; nt++) {
      int col = wn * 32 + nt * 8 + tig * 2;
      if (row0 < NN) *(__half2*)(g_y1h + (size_t)row0 * 128 + col) =
          __floats2half2_rn(acc[mt][nt][0], acc[mt][nt][1]);
      if (row1 < NN) *(__half2*)(g_y1h + (size_t)row1 * 128 + col) =
          __floats2half2_rn(acc[mt][nt][2], acc[mt][nt][3]);
    }
  }
}

// ---------------- merged kernels: gemm1 halves overlapped with hist / fill ----------------

__global__ void __launch_bounds__(THR_G, 2)
k_mergeA(const float* __restrict__ x, const int* __restrict__ ei) {
  if (blockIdx.x < GA_H1) {
    gemm1_body(blockIdx.x, x);
  } else {
    int hb = blockIdx.x - GA_H1;
    const int4* dst4 = (const int4*)(ei + EE);
    int stride = HB_BLK * THR_G;
    for (int e = hb * THR_G + threadIdx.x; e < EE / 4; e += stride) {
      int4 d = dst4[e];
      if ((unsigned)d.x < NN) atomicAdd(&g_cnt[d.x], 1);
      if ((unsigned)d.y < NN) atomicAdd(&g_cnt[d.y], 1);
      if ((unsigned)d.z < NN) atomicAdd(&g_cnt[d.z], 1);
      if ((unsigned)d.w < NN) atomicAdd(&g_cnt[d.w], 1);
    }
  }
}

__global__ void __launch_bounds__(THR_G, 2)
k_mergeB(const float* __restrict__ x, const int* __restrict__ ei) {
  if (blockIdx.x < GA_H2) {
    gemm1_body(GA_H1 + blockIdx.x, x);
  } else {
    int fb = blockIdx.x - GA_H2;
    const int2* src2 = (const int2*)ei;
    const int2* dst2 = (const int2*)(ei + EE);
    int stride = FB_BLK * THR_G;
    for (int e = fb * THR_G + threadIdx.x; e < EE / 2; e += stride) {
      int2 s = src2[e];
      int2 d = dst2[e];
      if ((unsigned)d.x < NN && (unsigned)s.x < NN)
        g_elist[atomicAdd(&g_cur[d.x], 1)] = s.x;
      if ((unsigned)d.y < NN && (unsigned)s.y < NN)
        g_elist[atomicAdd(&g_cur[d.y], 1)] = s.y;
    }
  }
}

// ---------------- gather: h = relu(y1[n] + sum_neighbors y1 + b1) -> fp16 ----------------

__global__ void __launch_bounds__(256, 6)
k_gather(const float* __restrict__ b1) {
  int warp = (blockIdx.x << 3) + (threadIdx.x >> 5);
  int lane = threadIdx.x & 31;
  const uint2* y1u = (const uint2*)g_y1h;
  float4 bb1 = *(const float4*)(b1 + lane * 4);

  int n0 = warp * RPW;
  if (n0 >= NN) return;
  int nend = n0 + RPW;
  if (nend > NN) nend = NN;

  int off_l = 0;
  if (lane <= RPW) {
    int idx = n0 + lane;
    if (idx > NN) idx = NN;
    off_l = g_off[idx];
  }

#pragma unroll 1
  for (int n = n0; n < nend; n++) {
    int r = n - n0;
    int lo = __shfl_sync(0xFFFFFFFFu, off_l, r);
    int hi = __shfl_sync(0xFFFFFFFFu, off_l, r + 1);

    uint2 u = y1u[(size_t)n * 32 + lane];
    float2 f0 = __half22float2(*(__half2*)&u.x);
    float2 f1 = __half22float2(*(__half2*)&u.y);
    float ax = f0.x, ay = f0.y, az = f1.x, aw = f1.y;
    int j = lo;
    for (; j + 8 <= hi; j += 8) {
#pragma unroll
      for (int q = 0; q < 8; q++) {
        int s0 = g_elist[j + q];
        uint2 v = y1u[(size_t)s0 * 32 + lane];
        float2 g0 = __half22float2(*(__half2*)&v.x);
        float2 g1 = __half22float2(*(__half2*)&v.y);
        ax += g0.x; ay += g0.y; az += g1.x; aw += g1.y;
      }
    }
    for (; j < hi; j++) {
      int s0 = g_elist[j];
      uint2 v = y1u[(size_t)s0 * 32 + lane];
      float2 g0 = __half22float2(*(__half2*)&v.x);
      float2 g1 = __half22float2(*(__half2*)&v.y);
      ax += g0.x; ay += g0.y; az += g1.x; aw += g1.y;
    }
    ax = fmaxf(ax + bb1.x, 0.f);
    ay = fmaxf(ay + bb1.y, 0.f);
    az = fmaxf(az + bb1.z, 0.f);
    aw = fmaxf(aw + bb1.w, 0.f);
    __half2 h0 = __floats2half2_rn(ax, ay);
    __half2 h1 = __floats2half2_rn(az, aw);
    uint2 o;
    o.x = *(unsigned*)&h0;
    o.y = *(unsigned*)&h1;
    ((uint2*)g_hh)[(size_t)n * 32 + lane] = o;
  }
}

// ---------------- gemm2: out = LN(h@W2 + b2)*gamma + beta + x@Wres + bres ----------------

__global__ void __launch_bounds__(THR_F, 1)
k_gemm2(const float* __restrict__ x, const float* __restrict__ b2,
        const float* __restrict__ gamma, const float* __restrict__ beta,
        const float* __restrict__ bres, float* __restrict__ out) {
  extern __shared__ __half smh[];
  __half* sH   = smh;                     // TM_F x SHH (h, then x)
  __half* sWT  = smh + TM_F * SHH;        // 128 (n) x SW2H (W2T, then WresT)
  float*  sPar = (float*)(smh + TM_F * SHH + 128 * SW2H);  // [b2|gamma|beta|bres]
  int tid = threadIdx.x;
  int warp = tid >> 5, lane = tid & 31;
  int base = blockIdx.x * TM_F;

  const uint4* w2src = (const uint4*)g_w2t;
  for (int i = tid; i < 128 * 16; i += THR_F) {
    int n = i >> 4, c = i & 15;
    *(uint4*)(sWT + n * SW2H + c * 8) = w2src[i];
  }
  for (int i = tid; i < 512; i += THR_F) {
    float v = (i < 128) ? b2[i]
            : (i < 256) ? gamma[i - 128]
            : (i < 384) ? beta[i - 256] : bres[i - 384];
    sPar[i] = v;
  }
  const uint2* hu = (const uint2*)g_hh;
  for (int i = tid; i < TM_F * 32; i += THR_F) {
    int row = i >> 5, c4 = i & 31;
    uint2 v = make_uint2(0u, 0u);
    if (base + row < NN) v = hu[(size_t)(base + row) * 32 + c4];
    *(uint2*)(sH + row * SHH + c4 * 4) = v;
  }
  __syncthreads();

  int gid = lane >> 2, tig = lane & 3;
  float acc[16][4];
#pragma unroll
  for (int nt = 0; nt < 16; nt++)
#pragma unroll
    for (int r = 0; r < 4; r++) acc[nt][r] = 0.f;

  const __half* pA = sH + (warp * 16 + gid) * SHH + tig * 2;
  const __half* pB = sWT + gid * SW2H + tig * 2;

  // Phase 1: acc = h @ W2
#pragma unroll
  for (int kk = 0; kk < 8; kk++) {
    unsigned a[4];
    const __half* p = pA + kk * 16;
    a[0] = ldh2(p);
    a[1] = ldh2(p + 8 * SHH);
    a[2] = ldh2(p + 8);
    a[3] = ldh2(p + 8 * SHH + 8);
#pragma unroll
    for (int nt = 0; nt < 16; nt++) {
      const __half* q = pB + nt * 8 * SW2H + kk * 16;
      unsigned b[2];
      b[0] = ldh2(q);
      b[1] = ldh2(q + 8);
      mma_f16(acc[nt], a, b);
    }
  }
  __syncthreads();   // all warps done reading sH / sWT before restage

  // Restage: x (fp16) -> sH, WresT -> sWT
  const uint4* wrsrc = (const uint4*)(g_wAt + 128 * 128);
  for (int i = tid; i < 128 * 16; i += THR_F) {
    int n = i >> 4, c = i & 15;
    *(uint4*)(sWT + n * SW2H + c * 8) = wrsrc[i];
  }
  const float4* x4 = (const float4*)x;
  for (int i = tid; i < TM_F * 32; i += THR_F) {
    int row = i >> 5, c4 = i & 31;
    float4 v = make_float4(0.f, 0.f, 0.f, 0.f);
    if (base + row < NN) v = x4[(size_t)(base + row) * 32 + c4];
    *(__half2*)(sH + row * SHH + c4 * 4)     = __floats2half2_rn(v.x, v.y);
    *(__half2*)(sH + row * SHH + c4 * 4 + 2) = __floats2half2_rn(v.z, v.w);
  }

  // LN on registers while restage is in flight.
  float s0 = 0.f, q0 = 0.f, s1 = 0.f, q1 = 0.f;
#pragma unroll
  for (int nt = 0; nt < 16; nt++) {
    int col = nt * 8 + tig * 2;
    float2 bb = *(const float2*)(sPar + col);
    acc[nt][0] += bb.x; acc[nt][1] += bb.y;
    acc[nt][2] += bb.x; acc[nt][3] += bb.y;
    s0 += acc[nt][0] + acc[nt][1];
    q0 += acc[nt][0] * acc[nt][0] + acc[nt][1] * acc[nt][1];
    s1 += acc[nt][2] + acc[nt][3];
    q1 += acc[nt][2] * acc[nt][2] + acc[nt][3] * acc[nt][3];
  }
#pragma unroll
  for (int o = 1; o < 4; o <<= 1) {
    s0 += __shfl_xor_sync(0xFFFFFFFFu, s0, o);
    q0 += __shfl_xor_sync(0xFFFFFFFFu, q0, o);
    s1 += __shfl_xor_sync(0xFFFFFFFFu, s1, o);
    q1 += __shfl_xor_sync(0xFFFFFFFFu, q1, o);
  }
  float mu0 = s0 * (1.f / 128.f);
  float mu1 = s1 * (1.f / 128.f);
  float rs0 = rsqrtf(q0 * (1.f / 128.f) - mu0 * mu0 + LN_EPS);
  float rs1 = rsqrtf(q1 * (1.f / 128.f) - mu1 * mu1 + LN_EPS);

#pragma unroll
  for (int nt = 0; nt < 16; nt++) {
    int col = nt * 8 + tig * 2;
    float2 gg = *(const float2*)(sPar + 128 + col);
    float2 be = *(const float2*)(sPar + 256 + col);
    acc[nt][0] = (acc[nt][0] - mu0) * rs0 * gg.x + be.x;
    acc[nt][1] = (acc[nt][1] - mu0) * rs0 * gg.y + be.y;
    acc[nt][2] = (acc[nt][2] - mu1) * rs1 * gg.x + be.x;
    acc[nt][3] = (acc[nt][3] - mu1) * rs1 * gg.y + be.y;
  }
  __syncthreads();

  // Phase 2: acc += x @ Wres
#pragma unroll
  for (int kk = 0; kk < 8; kk++) {
    unsigned a[4];
    const __half* p = pA + kk * 16;
    a[0] = ldh2(p);
    a[1] = ldh2(p + 8 * SHH);
    a[2] = ldh2(p + 8);
    a[3] = ldh2(p + 8 * SHH + 8);
#pragma unroll
    for (int nt = 0; nt < 16; nt++) {
      const __half* q = pB + nt * 8 * SW2H + kk * 16;
      unsigned b[2];
      b[0] = ldh2(q);
      b[1] = ldh2(q + 8);
      mma_f16(acc[nt], a, b);
    }
  }

  int row0 = base + warp * 16 + gid;
  int row1 = row0 + 8;
#pragma unroll
  for (int nt = 0; nt < 16; nt++) {
    int col = nt * 8 + tig * 2;
    float2 br = *(const float2*)(sPar + 384 + col);
    if (row0 < NN) {
      float2 o;
      o.x = acc[nt][0] + br.x;
      o.y = acc[nt][1] + br.y;
      *(float2*)(out + (size_t)row0 * 128 + col) = o;
    }
    if (row1 < NN) {
      float2 o;
      o.x = acc[nt][2] + br.x;
      o.y = acc[nt][3] + br.y;
      *(float2*)(out + (size_t)row1 * 128 + col) = o;
    }
  }
}

// ---------------- launch ----------------

extern "C" void kernel_launch(void* const* d_in, const int* in_sizes, int n_in,
                              void* d_out, int out_size) {
  const float* x     = (const float*)d_in[0];
  const int*   ei    = (const int*)  d_in[1];
  const float* W1    = (const float*)d_in[2];
  const float* b1    = (const float*)d_in[3];
  const float* W2    = (const float*)d_in[4];
  const float* b2    = (const float*)d_in[5];
  const float* gamma = (const float*)d_in[6];
  const float* beta  = (const float*)d_in[7];
  const float* Wres  = (const float*)d_in[8];
  const float* bres  = (const float*)d_in[9];
  float* out = (float*)d_out;

  cudaFuncSetAttribute(k_mergeA, cudaFuncAttributeMaxDynamicSharedMemorySize, SMEM_G);
  cudaFuncSetAttribute(k_mergeB, cudaFuncAttributeMaxDynamicSharedMemorySize, SMEM_G);
  cudaFuncSetAttribute(k_gemm2,  cudaFuncAttributeMaxDynamicSharedMemorySize, SMEM_F);

  k_prep<<<392, 256>>>(W1, Wres, W2);
  k_mergeA<<<GA_H1 + HB_BLK, THR_G, SMEM_G>>>(x, ei);
  k_scanLB<<<NB_S, 256>>>();
  k_mergeB<<<GA_H2 + FB_BLK, THR_G, SMEM_G>>>(x, ei);
  k_gather<<<GB_BLK, 256>>>(b1);
  k_gemm2<<<(NN + TM_F - 1) / TM_F, THR_F, SMEM_F>>>(x, b2, gamma, beta, bres, out);
}

// round 17
// speedup vs baseline: 1.1179x; 1.1179x over previous
#include <cuda_runtime.h>
#include <cuda_fp16.h>

#define NN 100000
#define EE 1600000
#define HID 128
#define LN_EPS 1e-5f

// ---- GEMM-1 config: block = 128 rows x 128 cols (W1 only), 512 thr ----
#define TM_A 128
#define THR_G 512
#define GA_TOT 782               // ceil(NN / TM_A)
#define HB_BLK 512               // hist blocks in mergeA
#define SXH 136
#define SWH 136
#define SMEM_G ((TM_A * SXH + 128 * SWH) * 2)

// ---- gemm2 config: block = 128 rows, warp = 16 rows x 64 cols, occ 2 ----
#define TM_F 128
#define THR_F 512
#define SHH 136
#define SW2H 136
#define SMEM_F ((TM_F * SHH + 128 * SW2H) * 2 + (512 + 512) * 4)

// ---- gather config ----
#define GB_BLK 1564
#define GW (GB_BLK * 8)          // 12512 warps
#define RPW ((NN + GW - 1) / GW) // 8 rows per warp

// ---- scan config (single-pass decoupled lookback) ----
#define NB_S 196
#define CHUNK_S 512

// ---- device scratch ----
__device__ int    g_cnt[NN];
__device__ int    g_cur[NN];
__device__ int    g_off[NN + 1];
__device__ int    g_pub[NB_S];   // packed (flag<<28)|value; 0 = not published
__device__ int    g_elist[EE];
__device__ __half g_wAt[256 * 128];  // [W1|Wres] transposed: [n][k], fp16
__device__ __half g_w2t[128 * 128];  // W2 transposed: [n][k], fp16
__device__ __half g_y1h[(size_t)NN * HID];
__device__ __half g_hh[(size_t)NN * HID];

// ---------------- helpers ----------------

__device__ __forceinline__ void mma_f16(float* c, const unsigned* a, const unsigned* b) {
  asm volatile(
      "mma.sync.aligned.m16n8k16.row.col.f32.f16.f16.f32 "
      "{%0,%1,%2,%3}, {%4,%5,%6,%7}, {%8,%9}, {%0,%1,%2,%3};"
      : "+f"(c[0]), "+f"(c[1]), "+f"(c[2]), "+f"(c[3])
      : "r"(a[0]), "r"(a[1]), "r"(a[2]), "r"(a[3]), "r"(b[0]), "r"(b[1]));
}

__device__ __forceinline__ unsigned ldh2(const __half* p) {
  return *(const unsigned*)p;
}

// ---------------- prep: zero counters + one-time weight convert/transpose ----------------

__global__ void k_prep(const float* __restrict__ W1, const float* __restrict__ Wres,
                       const float* __restrict__ W2) {
  int stride = gridDim.x * blockDim.x;
  int t0 = blockIdx.x * blockDim.x + threadIdx.x;
  for (int i = t0; i < NN; i += stride) g_cnt[i] = 0;
  if (t0 < NB_S) g_pub[t0] = 0;
  for (int i = t0; i < 256 * 128; i += stride) {
    int n = i >> 7, k = i & 127;
    float v = (n < 128) ? W1[k * 128 + n] : Wres[k * 128 + (n - 128)];
    g_wAt[i] = __float2half_rn(v);
  }
  for (int i = t0; i < 128 * 128; i += stride) {
    int n = i >> 7, k = i & 127;
    g_w2t[i] = __float2half_rn(W2[k * 128 + n]);
  }
}

// ---------------- single-pass scan (decoupled lookback) ----------------

__global__ void k_scanLB() {
  __shared__ int s[256];
  __shared__ int s_excl;
  int b = blockIdx.x, t = threadIdx.x;
  int i0 = b * CHUNK_S + t * 2;
  int c0 = (i0 < NN) ? g_cnt[i0] : 0;
  int c1 = (i0 + 1 < NN) ? g_cnt[i0 + 1] : 0;
  s[t] = c0 + c1;
  __syncthreads();
#pragma unroll
  for (int d = 1; d < 256; d <<= 1) {
    int v = (t >= d) ? s[t - d] : 0;
    __syncthreads();
    s[t] += v;
    __syncthreads();
  }
  int total = s[255];
  if (t == 0) {
    if (b == 0) {
      atomicExch(&g_pub[0], (2 << 28) | total);
      s_excl = 0;
    } else {
      atomicExch(&g_pub[b], (1 << 28) | total);
      int excl = 0, p = b - 1;
      while (1) {
        int w = atomicAdd(&g_pub[p], 0);
        if (w == 0) { __nanosleep(40); continue; }
        excl += w & 0x0FFFFFFF;
        if ((w >> 28) == 2) break;
        p--;
      }
      atomicExch(&g_pub[b], (2 << 28) | (excl + total));
      s_excl = excl;
    }
  }
  __syncthreads();
  int base = s_excl + ((t == 0) ? 0 : s[t - 1]);
  if (i0 < NN)     { g_off[i0] = base;          g_cur[i0] = base; }
  if (i0 + 1 < NN) { g_off[i0 + 1] = base + c0; g_cur[i0 + 1] = base + c0; }
  if (b == NB_S - 1 && t == 255) g_off[NN] = s_excl + total;
}

// ---------------- gemm1 body: y1 = x@W1 (128 rows x 128 cols, acc=32 regs) ----------------

__device__ __forceinline__ void gemm1_body(int ba, const float* __restrict__ x) {
  extern __shared__ __half smh[];
  __half* sX  = smh;
  __half* sWT = smh + TM_A * SXH;
  int tid = threadIdx.x;
  int base = ba * TM_A;

  const uint4* wsrc = (const uint4*)g_wAt;   // W1 half
  for (int i = tid; i < 128 * 16; i += THR_G) {
    int n = i >> 4, c = i & 15;
    *(uint4*)(sWT + n * SWH + c * 8) = wsrc[i];
  }
  const float4* x4 = (const float4*)x;
  for (int i = tid; i < TM_A * 32; i += THR_G) {
    int row = i >> 5, c4 = i & 31;
    float4 v = make_float4(0.f, 0.f, 0.f, 0.f);
    if (base + row < NN) v = x4[(size_t)(base + row) * 32 + c4];
    *(__half2*)(sX + row * SXH + c4 * 4)     = __floats2half2_rn(v.x, v.y);
    *(__half2*)(sX + row * SXH + c4 * 4 + 2) = __floats2half2_rn(v.z, v.w);
  }
  __syncthreads();

  int warp = tid >> 5, lane = tid & 31;
  int gid = lane >> 2, tig = lane & 3;
  int wm = warp >> 2, wn = warp & 3;

  float acc[2][4][4];
#pragma unroll
  for (int mt = 0; mt < 2; mt++)
#pragma unroll
    for (int nt = 0; nt < 4; nt++)
#pragma unroll
      for (int r = 0; r < 4; r++) acc[mt][nt][r] = 0.f;

  const __half* pA = sX + (wm * 32 + gid) * SXH + tig * 2;
  const __half* pB = sWT + (wn * 32 + gid) * SWH + tig * 2;

#pragma unroll
  for (int kk = 0; kk < 8; kk++) {
    unsigned a[2][4];
#pragma unroll
    for (int mt = 0; mt < 2; mt++) {
      const __half* p = pA + mt * 16 * SXH + kk * 16;
      a[mt][0] = ldh2(p);
      a[mt][1] = ldh2(p + 8 * SXH);
      a[mt][2] = ldh2(p + 8);
      a[mt][3] = ldh2(p + 8 * SXH + 8);
    }
#pragma unroll
    for (int nt = 0; nt < 4; nt++) {
      const __half* q = pB + nt * 8 * SWH + kk * 16;
      unsigned b[2];
      b[0] = ldh2(q);
      b[1] = ldh2(q + 8);
      mma_f16(acc[0][nt], a[0], b);
      mma_f16(acc[1][nt], a[1], b);
    }
  }

#pragma unroll
  for (int mt = 0; mt < 2; mt++) {
    int row0 = base + wm * 32 + mt * 16 + gid;
    int row1 = row0 + 8;
#pragma unroll
    for (int nt = 0; nt < 4; nt++) {
      int col = wn * 32 + nt * 8 + tig * 2;
      if (row0 < NN) *(__half2*)(g_y1h + (size_t)row0 * 128 + col) =
          __floats2half2_rn(acc[mt][nt][0], acc[mt][nt][1]);
      if (row1 < NN) *(__half2*)(g_y1h + (size_t)row1 * 128 + col) =
          __floats2half2_rn(acc[mt][nt][2], acc[mt][nt][3]);
    }
  }
}

// ---------------- mergeA: all gemm1 blocks + hist ----------------

__global__ void __launch_bounds__(THR_G, 2)
k_mergeA(const float* __restrict__ x, const int* __restrict__ ei) {
  if (blockIdx.x < GA_TOT) {
    gemm1_body(blockIdx.x, x);
  } else {
    int hb = blockIdx.x - GA_TOT;
    const int4* dst4 = (const int4*)(ei + EE);
    int stride = HB_BLK * THR_G;
    for (int e = hb * THR_G + threadIdx.x; e < EE / 4; e += stride) {
      int4 d = dst4[e];
      if ((unsigned)d.x < NN) atomicAdd(&g_cnt[d.x], 1);
      if ((unsigned)d.y < NN) atomicAdd(&g_cnt[d.y], 1);
      if ((unsigned)d.z < NN) atomicAdd(&g_cnt[d.z], 1);
      if ((unsigned)d.w < NN) atomicAdd(&g_cnt[d.w], 1);
    }
  }
}

// ---------------- fill (lean, high-occupancy) ----------------

__global__ void k_fill(const int* __restrict__ ei) {
  const int2* src2 = (const int2*)ei;
  const int2* dst2 = (const int2*)(ei + EE);
  int stride = gridDim.x * blockDim.x;
  for (int e = blockIdx.x * blockDim.x + threadIdx.x; e < EE / 2; e += stride) {
    int2 s = src2[e];
    int2 d = dst2[e];
    if ((unsigned)d.x < NN && (unsigned)s.x < NN)
      g_elist[atomicAdd(&g_cur[d.x], 1)] = s.x;
    if ((unsigned)d.y < NN && (unsigned)s.y < NN)
      g_elist[atomicAdd(&g_cur[d.y], 1)] = s.y;
  }
}

// ---------------- gather: h = relu(y1[n] + sum_neighbors y1 + b1) -> fp16 ----------------

__global__ void __launch_bounds__(256, 6)
k_gather(const float* __restrict__ b1) {
  int warp = (blockIdx.x << 3) + (threadIdx.x >> 5);
  int lane = threadIdx.x & 31;
  const uint2* y1u = (const uint2*)g_y1h;
  float4 bb1 = *(const float4*)(b1 + lane * 4);

  int n0 = warp * RPW;
  if (n0 >= NN) return;
  int nend = n0 + RPW;
  if (nend > NN) nend = NN;

  int off_l = 0;
  if (lane <= RPW) {
    int idx = n0 + lane;
    if (idx > NN) idx = NN;
    off_l = g_off[idx];
  }

#pragma unroll 1
  for (int n = n0; n < nend; n++) {
    int r = n - n0;
    int lo = __shfl_sync(0xFFFFFFFFu, off_l, r);
    int hi = __shfl_sync(0xFFFFFFFFu, off_l, r + 1);

    uint2 u = y1u[(size_t)n * 32 + lane];
    float2 f0 = __half22float2(*(__half2*)&u.x);
    float2 f1 = __half22float2(*(__half2*)&u.y);
    float ax = f0.x, ay = f0.y, az = f1.x, aw = f1.y;
    int j = lo;
    for (; j + 8 <= hi; j += 8) {
#pragma unroll
      for (int q = 0; q < 8; q++) {
        int s0 = g_elist[j + q];
        uint2 v = y1u[(size_t)s0 * 32 + lane];
        float2 g0 = __half22float2(*(__half2*)&v.x);
        float2 g1 = __half22float2(*(__half2*)&v.y);
        ax += g0.x; ay += g0.y; az += g1.x; aw += g1.y;
      }
    }
    for (; j < hi; j++) {
      int s0 = g_elist[j];
      uint2 v = y1u[(size_t)s0 * 32 + lane];
      float2 g0 = __half22float2(*(__half2*)&v.x);
      float2 g1 = __half22float2(*(__half2*)&v.y);
      ax += g0.x; ay += g0.y; az += g1.x; aw += g1.y;
    }
    ax = fmaxf(ax + bb1.x, 0.f);
    ay = fmaxf(ay + bb1.y, 0.f);
    az = fmaxf(az + bb1.z, 0.f);
    aw = fmaxf(aw + bb1.w, 0.f);
    __half2 h0 = __floats2half2_rn(ax, ay);
    __half2 h1 = __floats2half2_rn(az, aw);
    uint2 o;
    o.x = *(unsigned*)&h0;
    o.y = *(unsigned*)&h1;
    ((uint2*)g_hh)[(size_t)n * 32 + lane] = o;
  }
}

// ---------------- gemm2 (occ 2): out = LN(h@W2 + b2)*gamma + beta + x@Wres + bres ----------------
// 512 thr = 16 warps. Block tile 128 rows. Warp (wg=warp>>1, wn=warp&1):
// 16 rows x 64 cols, acc[8][4] = 32 regs. LN partials combined across wn via smem.

__global__ void __launch_bounds__(THR_F, 2)
k_gemm2(const float* __restrict__ x, const float* __restrict__ b2,
        const float* __restrict__ gamma, const float* __restrict__ beta,
        const float* __restrict__ bres, float* __restrict__ out) {
  extern __shared__ __half smh[];
  __half* sH   = smh;                     // TM_F x SHH (h, then x)
  __half* sWT  = smh + TM_F * SHH;        // 128 (n) x SW2H (W2T, then WresT)
  float*  sPar = (float*)(smh + TM_F * SHH + 128 * SW2H);  // [b2|gamma|beta|bres]
  float*  sS   = sPar + 512;              // [128 rows][2 halves]
  float*  sQ   = sS + 256;                // [128 rows][2 halves]
  int tid = threadIdx.x;
  int warp = tid >> 5, lane = tid & 31;
  int base = blockIdx.x * TM_F;

  const uint4* w2src = (const uint4*)g_w2t;
  for (int i = tid; i < 128 * 16; i += THR_F) {
    int n = i >> 4, c = i & 15;
    *(uint4*)(sWT + n * SW2H + c * 8) = w2src[i];
  }
  for (int i = tid; i < 512; i += THR_F) {
    float v = (i < 128) ? b2[i]
            : (i < 256) ? gamma[i - 128]
            : (i < 384) ? beta[i - 256] : bres[i - 384];
    sPar[i] = v;
  }
  const uint2* hu = (const uint2*)g_hh;
  for (int i = tid; i < TM_F * 32; i += THR_F) {
    int row = i >> 5, c4 = i & 31;
    uint2 v = make_uint2(0u, 0u);
    if (base + row < NN) v = hu[(size_t)(base + row) * 32 + c4];
    *(uint2*)(sH + row * SHH + c4 * 4) = v;
  }
  __syncthreads();

  int gid = lane >> 2, tig = lane & 3;
  int wg = warp >> 1, wn = warp & 1;

  float acc[8][4];
#pragma unroll
  for (int nt = 0; nt < 8; nt++)
#pragma unroll
    for (int r = 0; r < 4; r++) acc[nt][r] = 0.f;

  const __half* pA = sH + (wg * 16 + gid) * SHH + tig * 2;
  const __half* pB = sWT + (wn * 64 + gid) * SW2H + tig * 2;

  // Phase 1: acc = h @ W2 (this warp's 64-col half)
#pragma unroll
  for (int kk = 0; kk < 8; kk++) {
    unsigned a[4];
    const __half* p = pA + kk * 16;
    a[0] = ldh2(p);
    a[1] = ldh2(p + 8 * SHH);
    a[2] = ldh2(p + 8);
    a[3] = ldh2(p + 8 * SHH + 8);
#pragma unroll
    for (int nt = 0; nt < 8; nt++) {
      const __half* q = pB + nt * 8 * SW2H + kk * 16;
      unsigned b[2];
      b[0] = ldh2(q);
      b[1] = ldh2(q + 8);
      mma_f16(acc[nt], a, b);
    }
  }

  // +b2 and partial LN sums over this warp's 64 cols
  float s0 = 0.f, q0 = 0.f, s1 = 0.f, q1 = 0.f;
#pragma unroll
  for (int nt = 0; nt < 8; nt++) {
    int col = wn * 64 + nt * 8 + tig * 2;
    float2 bb = *(const float2*)(sPar + col);
    acc[nt][0] += bb.x; acc[nt][1] += bb.y;
    acc[nt][2] += bb.x; acc[nt][3] += bb.y;
    s0 += acc[nt][0] + acc[nt][1];
    q0 += acc[nt][0] * acc[nt][0] + acc[nt][1] * acc[nt][1];
    s1 += acc[nt][2] + acc[nt][3];
    q1 += acc[nt][2] * acc[nt][2] + acc[nt][3] * acc[nt][3];
  }
#pragma unroll
  for (int o = 1; o < 4; o <<= 1) {
    s0 += __shfl_xor_sync(0xFFFFFFFFu, s0, o);
    q0 += __shfl_xor_sync(0xFFFFFFFFu, q0, o);
    s1 += __shfl_xor_sync(0xFFFFFFFFu, s1, o);
    q1 += __shfl_xor_sync(0xFFFFFFFFu, q1, o);
  }
  int r0 = wg * 16 + gid, r1 = r0 + 8;
  if (tig == 0) {
    sS[r0 * 2 + wn] = s0; sQ[r0 * 2 + wn] = q0;
    sS[r1 * 2 + wn] = s1; sQ[r1 * 2 + wn] = q1;
  }
  __syncthreads();   // sS/sQ visible; phase-1 reads of sH/sWT complete

  // Restage: x (fp16) -> sH, WresT -> sWT
  const uint4* wrsrc = (const uint4*)(g_wAt + 128 * 128);
  for (int i = tid; i < 128 * 16; i += THR_F) {
    int n = i >> 4, c = i & 15;
    *(uint4*)(sWT + n * SW2H + c * 8) = wrsrc[i];
  }
  const float4* x4 = (const float4*)x;
  for (int i = tid; i < TM_F * 32; i += THR_F) {
    int row = i >> 5, c4 = i & 31;
    float4 v = make_float4(0.f, 0.f, 0.f, 0.f);
    if (base + row < NN) v = x4[(size_t)(base + row) * 32 + c4];
    *(__half2*)(sH + row * SHH + c4 * 4)     = __floats2half2_rn(v.x, v.y);
    *(__half2*)(sH + row * SHH + c4 * 4 + 2) = __floats2half2_rn(v.z, v.w);
  }

  // LN totals + transform acc while restage is in flight
  float S0 = sS[r0 * 2] + sS[r0 * 2 + 1];
  float Q0 = sQ[r0 * 2] + sQ[r0 * 2 + 1];
  float S1 = sS[r1 * 2] + sS[r1 * 2 + 1];
  float Q1 = sQ[r1 * 2] + sQ[r1 * 2 + 1];
  float mu0 = S0 * (1.f / 128.f);
  float mu1 = S1 * (1.f / 128.f);
  float rs0 = rsqrtf(Q0 * (1.f / 128.f) - mu0 * mu0 + LN_EPS);
  float rs1 = rsqrtf(Q1 * (1.f / 128.f) - mu1 * mu1 + LN_EPS);

#pragma unroll
  for (int nt = 0; nt < 8; nt++) {
    int col = wn * 64 + nt * 8 + tig * 2;
    float2 gg = *(const float2*)(sPar + 128 + col);
    float2 be = *(const float2*)(sPar + 256 + col);
    acc[nt][0] = (acc[nt][0] - mu0) * rs0 * gg.x + be.x;
    acc[nt][1] = (acc[nt][1] - mu0) * rs0 * gg.y + be.y;
    acc[nt][2] = (acc[nt][2] - mu1) * rs1 * gg.x + be.x;
    acc[nt][3] = (acc[nt][3] - mu1) * rs1 * gg.y + be.y;
  }
  __syncthreads();

  // Phase 2: acc += x @ Wres
#pragma unroll
  for (int kk = 0; kk < 8; kk++) {
    unsigned a[4];
    const __half* p = pA + kk * 16;
    a[0] = ldh2(p);
    a[1] = ldh2(p + 8 * SHH);
    a[2] = ldh2(p + 8);
    a[3] = ldh2(p + 8 * SHH + 8);
#pragma unroll
    for (int nt = 0; nt < 8; nt++) {
      const __half* q = pB + nt * 8 * SW2H + kk * 16;
      unsigned b[2];
      b[0] = ldh2(q);
      b[1] = ldh2(q + 8);
      mma_f16(acc[nt], a, b);
    }
  }

  int row0 = base + r0;
  int row1 = base + r1;
#pragma unroll
  for (int nt = 0; nt < 8; nt++) {
    int col = wn * 64 + nt * 8 + tig * 2;
    float2 br = *(const float2*)(sPar + 384 + col);
    if (row0 < NN) {
      float2 o;
      o.x = acc[nt][0] + br.x;
      o.y = acc[nt][1] + br.y;
      *(float2*)(out + (size_t)row0 * 128 + col) = o;
    }
    if (row1 < NN) {
      float2 o;
      o.x = acc[nt][2] + br.x;
      o.y = acc[nt][3] + br.y;
      *(float2*)(out + (size_t)row1 * 128 + col) = o;
    }
  }
}

// ---------------- launch ----------------

extern "C" void kernel_launch(void* const* d_in, const int* in_sizes, int n_in,
                              void* d_out, int out_size) {
  const float* x     = (const float*)d_in[0];
  const int*   ei    = (const int*)  d_in[1];
  const float* W1    = (const float*)d_in[2];
  const float* b1    = (const float*)d_in[3];
  const float* W2    = (const float*)d_in[4];
  const float* b2    = (const float*)d_in[5];
  const float* gamma = (const float*)d_in[6];
  const float* beta  = (const float*)d_in[7];
  const float* Wres  = (const float*)d_in[8];
  const float* bres  = (const float*)d_in[9];
  float* out = (float*)d_out;

  cudaFuncSetAttribute(k_mergeA, cudaFuncAttributeMaxDynamicSharedMemorySize, SMEM_G);
  cudaFuncSetAttribute(k_gemm2,  cudaFuncAttributeMaxDynamicSharedMemorySize, SMEM_F);

  k_prep<<<392, 256>>>(W1, Wres, W2);
  k_mergeA<<<GA_TOT + HB_BLK, THR_G, SMEM_G>>>(x, ei);
  k_scanLB<<<NB_S, 256>>>();
  k_fill<<<2048, 256>>>(ei);
  k_gather<<<GB_BLK, 256>>>(b1);
  k_gemm2<<<(NN + TM_F - 1) / TM_F, THR_F, SMEM_F>>>(x, b2, gamma, beta, bres, out);
}